// round 16
// baseline (speedup 1.0000x reference)
#include <cuda_runtime.h>
#include <cstdint>

#define Bb 32
#define Tt 4096
#define Dd 512
#define Hh 8
#define HD 64
#define SCALE 0.125f

#define TILE 16
#define NC2 32
#define CH2 (Tt/NC2)        // 128 tokens per chunk
#define NTILES (CH2/TILE)   // 8 tiles

typedef unsigned long long ull;

// ---------------- helpers ----------------
__device__ __forceinline__ uint32_t s2u(const void* p) {
    uint32_t a; asm("{ .reg .u64 t; cvta.to.shared.u64 t, %1; cvt.u32.u64 %0, t; }" : "=r"(a) : "l"(p));
    return a;
}
__device__ __forceinline__ float lds32f(uint32_t addr) {
    float v; asm("ld.shared.f32 %0,[%1];" : "=f"(v) : "r"(addr)); return v;
}
__device__ __forceinline__ uint32_t lds32u(uint32_t addr) {
    uint32_t v; asm("ld.shared.b32 %0,[%1];" : "=r"(v) : "r"(addr)); return v;
}
__device__ __forceinline__ uint32_t f2tf(float f) {
    uint32_t r; asm("cvt.rna.tf32.f32 %0,%1;" : "=r"(r) : "f"(f)); return r;
}
__device__ __forceinline__ void cp16(uint32_t smem, const void* g) {
    asm volatile("cp.async.cg.shared.global [%0], [%1], 16;" :: "r"(smem), "l"(g) : "memory");
}
__device__ __forceinline__ void cp_commit() {
    asm volatile("cp.async.commit_group;" ::: "memory");
}
__device__ __forceinline__ void cp_wait1() {
    asm volatile("cp.async.wait_group 1;" ::: "memory");
}
__device__ __forceinline__ void redg_add(float* p, float v) {
    asm volatile("red.global.add.f32 [%0], %1;" :: "l"(p), "f"(v) : "memory");
}
__device__ __forceinline__ float4 ldg_cg4(const float* p) {
    float4 v;
    asm volatile("ld.global.cg.v4.f32 {%0,%1,%2,%3},[%4];"
        : "=f"(v.x), "=f"(v.y), "=f"(v.z), "=f"(v.w) : "l"(p));
    return v;
}
__device__ __forceinline__ float ldg_cg1(const float* p) {
    float v; asm volatile("ld.global.cg.f32 %0,[%1];" : "=f"(v) : "l"(p)); return v;
}
__device__ __forceinline__ void mma_tf32(float& c0, float& c1, float& c2, float& c3,
                                         uint32_t a0, uint32_t a1, uint32_t a2, uint32_t a3,
                                         uint32_t b0, uint32_t b1) {
    asm volatile("mma.sync.aligned.m16n8k8.row.col.f32.tf32.tf32.f32 "
                 "{%0,%1,%2,%3},{%4,%5,%6,%7},{%8,%9},{%0,%1,%2,%3};"
                 : "+f"(c0), "+f"(c1), "+f"(c2), "+f"(c3)
                 : "r"(a0), "r"(a1), "r"(a2), "r"(a3), "r"(b0), "r"(b1));
}

// ---------------- static scratch ----------------
__device__ float g_q[Bb*Dd];
__device__ float g_u[Bb*Hh*Dd];                 // SCALE folded in
__device__ float g_scores[(size_t)Bb*Tt*Hh];    // raw logits, 4MB
__device__ float g_L[Bb*Hh];                    // atomically accumulated
__device__ float g_cacc[Bb*Hh*Dd];              // atomically accumulated ctilde (unnorm)
__device__ float g_ctx[Bb*Dd];
__device__ int   g_gate;    // k_vwo internal gate (reset by k_qu2)
__device__ int   g_gate2;   // k_qu2 internal gate (reset by k_vwo)

// ---------------- K0: fused q + u with in-kernel gate ----------------
// grid 320 (all co-resident): bid<64 -> q phase (block = 8 outputs);
// bid>=64 -> (h,b) u phase: zero accumulators, spin on gate, compute u.
__global__ void __launch_bounds__(256) k_qu2(const float* __restrict__ enc,
                                             const float* __restrict__ Wq,
                                             const float* __restrict__ Wk) {
    extern __shared__ float esh[];
    int tid = threadIdx.x, w = tid >> 5, lane = tid & 31;
    int bid = blockIdx.x;

    if (bid < 64) {
        // ---- q phase (identical math to old k_q) ----
        {
            float4* dst = (float4*)esh;
            #pragma unroll
            for (int i = 0; i < 16; i++) {
                int idx = tid + i*256;
                int bb = idx >> 7, j4 = idx & 127;
                dst[idx] = *(const float4*)&enc[((size_t)bb*Tt + (Tt-1))*Dd + j4*4];
            }
        }
        int o = bid*8 + w;
        float4 wr[4];
        #pragma unroll
        for (int k = 0; k < 4; k++)
            wr[k] = *(const float4*)&Wq[(size_t)o*Dd + k*128 + lane*4];
        __syncthreads();
        for (int bb = 0; bb < Bb; bb++) {
            float4 e0 = *(const float4*)&esh[bb*Dd + 0*128 + lane*4];
            float4 e1 = *(const float4*)&esh[bb*Dd + 1*128 + lane*4];
            float4 e2 = *(const float4*)&esh[bb*Dd + 2*128 + lane*4];
            float4 e3 = *(const float4*)&esh[bb*Dd + 3*128 + lane*4];
            float s;
            s  = e0.x*wr[0].x + e0.y*wr[0].y + e0.z*wr[0].z + e0.w*wr[0].w;
            s += e1.x*wr[1].x + e1.y*wr[1].y + e1.z*wr[1].z + e1.w*wr[1].w;
            s += e2.x*wr[2].x + e2.y*wr[2].y + e2.z*wr[2].z + e2.w*wr[2].w;
            s += e3.x*wr[3].x + e3.y*wr[3].y + e3.z*wr[3].z + e3.w*wr[3].w;
            #pragma unroll
            for (int off = 16; off; off >>= 1) s += __shfl_xor_sync(0xffffffffu, s, off);
            if (lane == 0) g_q[bb*Dd + o] = s;
        }
        __threadfence();
        __syncthreads();
        if (tid == 0) atomicAdd(&g_gate2, 1);
    } else {
        // ---- u phase ----
        int id = bid - 64;
        int h = id & 7, b = id >> 3;
        // replay-safe zeroing (overlaps the spin latency)
        g_cacc[((size_t)b*Hh + h)*Dd + tid] = 0.f;
        g_cacc[((size_t)b*Hh + h)*Dd + 256 + tid] = 0.f;
        if (tid == 0 && id == 0) g_gate = 0;
        if (tid == 0) g_L[b*Hh + h] = 0.f;
        // spin until all 64 q blocks done
        if (tid == 0) { while (atomicAdd(&g_gate2, 0) < 64) { } }
        __syncthreads();
        float* qsh = esh;
        if (tid < HD) qsh[tid] = ldg_cg1(&g_q[b*Dd + h*HD + tid]);
        __syncthreads();
        #pragma unroll
        for (int r = 0; r < 2; r++) {
            int j = tid + r*256;
            float s = 0.f;
            #pragma unroll 8
            for (int i = 0; i < HD; i++)
                s += Wk[((size_t)(h*HD + i))*Dd + j] * qsh[i];
            g_u[((size_t)b*Hh + h)*Dd + j] = s * SCALE;
        }
    }
}

// ---------------- smem layout of k_fused (float offsets) ----------------
// esh[2][16][512] swizzled   @ 0      (16384 floats)
// csh[8][128]                @ 16384  (1024)
// ew[16][12] (tf32 bits)     @ 17408  (192)
// lred[128]                  @ 17664  (128)
#define OFF_CSH  16384
#define OFF_EW   17408
#define OFF_LRED 17664
#define FUSED_SMEM (17792*4)

// Swizzle: element (t, d) stored at float-index  t*512 + ((q ^ (t&7))<<2) + (d&3),  q = d>>2.

// ---------------- K1: tf32-MMA scores + exp + tf32-MMA weighted accumulate ----------------
__global__ void __launch_bounds__(256, 3) k_fused(const float* __restrict__ enc) {
    extern __shared__ float sm[];
    uint32_t base_u = s2u(sm);
    uint32_t esh_u0 = base_u;
    uint32_t csh_u  = base_u + OFF_CSH*4;
    uint32_t ew_u   = base_u + OFF_EW*4;
    float* csh  = sm + OFF_CSH;
    float* lred = sm + OFF_LRED;
    uint32_t* smu = (uint32_t*)sm;

    int tid = threadIdx.x, w = tid >> 5, lane = tid & 31;
    int b = blockIdx.x >> 5, c = blockIdx.x & (NC2-1);
    int g  = lane >> 2;         // mma group id
    int tg = lane & 3;          // thread-in-group

    // ---- score-phase B fragments: U k-slice [w*64, w*64+64), tf32 (rounded once) ----
    uint32_t bf0[8], bf1[8];
    {
        const float* ub = &g_u[(size_t)b*Hh*Dd];   // [h][d]
        #pragma unroll
        for (int ks = 0; ks < 8; ks++) {
            int d = w*64 + ks*8 + tg;
            bf0[ks] = f2tf(ub[(size_t)g*Dd + d]);
            bf1[ks] = f2tf(ub[(size_t)g*Dd + d + 4]);
        }
    }

    int tbase = c * CH2;
    const float* encb = enc + ((size_t)b*Tt + tbase)*Dd;

    // ---- cp.async tile loader (swizzled) ----
    auto load_tile = [&](int tile) {
        const float* src = encb + (size_t)tile*TILE*Dd;
        #pragma unroll
        for (int j = 0; j < 8; j++) {
            int id = tid + j*256;          // 2048 chunks of 16B
            int t = id >> 7, q = id & 127;
            uint32_t saddr = esh_u0 + ((tile & 1) ? TILE*Dd*4 : 0)
                           + (uint32_t)(t*2048 + ((q ^ (t & 7)) << 4));
            cp16(saddr, src + (size_t)t*Dd + q*4);
        }
    };

    load_tile(0); cp_commit();
    load_tile(1); cp_commit();

    // ---- persistent context accumulators: warp w owns d in [w*64, w*64+64) ----
    float C[4][4];
    #pragma unroll
    for (int j = 0; j < 4; j++)
        #pragma unroll
        for (int r = 0; r < 4; r++) C[j][r] = 0.f;
    float l_priv = 0.f;

    for (int i = 0; i < NTILES; i++) {
        uint32_t esh_u = esh_u0 + (i & 1)*TILE*Dd*4;
        cp_wait1();
        __syncthreads();

        // ---- score phase: warp w = k-slice, mma m16n8k8 tf32 ----
        {
            float c0 = 0.f, c1 = 0.f, c2 = 0.f, c3 = 0.f;
            #pragma unroll
            for (int ks = 0; ks < 8; ks++) {
                uint32_t q  = (uint32_t)(w*16 + ks*2);
                uint32_t x0 = (q ^ (uint32_t)g) << 4;
                uint32_t x2 = ((q+1) ^ (uint32_t)g) << 4;
                uint32_t rb0 = esh_u + (uint32_t)(g*2048 + tg*4);
                uint32_t rb1 = esh_u + (uint32_t)((g+8)*2048 + tg*4);
                uint32_t a0 = f2tf(lds32f(rb0 + x0));
                uint32_t a1 = f2tf(lds32f(rb1 + x0));
                uint32_t a2 = f2tf(lds32f(rb0 + x2));
                uint32_t a3 = f2tf(lds32f(rb1 + x2));
                mma_tf32(c0, c1, c2, c3, a0, a1, a2, a3, bf0[ks], bf1[ks]);
            }
            asm volatile("st.shared.v4.f32 [%0],{%1,%2,%3,%4};"
                :: "r"(csh_u + (uint32_t)((w*128 + lane*4)*4)),
                   "f"(c0), "f"(c1), "f"(c2), "f"(c3) : "memory");
        }
        __syncthreads();

        // ---- reduce partials across warps, exp, publish tf32 weights (stride-12) ----
        if (tid < 128) {
            float s = csh[tid];
            #pragma unroll
            for (int ww = 1; ww < 8; ww++) s += csh[ww*128 + tid];
            int r = tid & 3, l2 = tid >> 2;
            int row = (l2 >> 2) + ((r >> 1) << 3);     // token row in tile
            int col = ((l2 & 3) << 1) + (r & 1);       // head
            g_scores[((size_t)b*Tt + tbase + i*TILE + row)*Hh + col] = s;
            float we = __expf(s);
            l_priv += we;
            smu[OFF_EW + row*12 + col] = f2tf(we);     // pre-converted tf32 bits
        }
        __syncthreads();

        // ---- accumulate via MMA: C(d x h) += E^T . W, k-permuted rows ----
        #pragma unroll
        for (int j = 0; j < 4; j++) {
            int mt = w*4 + j;
            #pragma unroll
            for (int ks = 0; ks < 2; ks++) {
                int r0 = ks*8 + 2*tg;
                int r1 = r0 + 1;
                int q0 = mt*4 + (g >> 2);
                int q1 = q0 + 2;
                uint32_t base0 = esh_u + (uint32_t)(r0*2048 + (g & 3)*4);
                uint32_t base1 = esh_u + (uint32_t)(r1*2048 + (g & 3)*4);
                uint32_t a0 = f2tf(lds32f(base0 + (uint32_t)(((q0 ^ (r0 & 7)) << 4))));
                uint32_t a1 = f2tf(lds32f(base0 + (uint32_t)(((q1 ^ (r0 & 7)) << 4))));
                uint32_t a2 = f2tf(lds32f(base1 + (uint32_t)(((q0 ^ (r1 & 7)) << 4))));
                uint32_t a3 = f2tf(lds32f(base1 + (uint32_t)(((q1 ^ (r1 & 7)) << 4))));
                uint32_t b0 = lds32u(ew_u + (uint32_t)((r0*12 + g)*4));
                uint32_t b1 = lds32u(ew_u + (uint32_t)((r1*12 + g)*4));
                mma_tf32(C[j][0], C[j][1], C[j][2], C[j][3], a0, a1, a2, a3, b0, b1);
            }
        }
        __syncthreads();   // buffer (i&1) fully consumed

        if (i + 2 < NTILES) load_tile(i + 2);
        cp_commit();       // uniform group count even when no loads issued
    }

    // ---- chunk outputs: RED.ADD C frags into g_cacc ----
    {
        float* pb = &g_cacc[((size_t)b*Hh)*Dd];
        #pragma unroll
        for (int j = 0; j < 4; j++) {
            int d = (w*4 + j)*16 + g;
            redg_add(&pb[(size_t)(2*tg)*Dd + d],       C[j][0]);
            redg_add(&pb[(size_t)(2*tg+1)*Dd + d],     C[j][1]);
            redg_add(&pb[(size_t)(2*tg)*Dd + d + 8],   C[j][2]);
            redg_add(&pb[(size_t)(2*tg+1)*Dd + d + 8], C[j][3]);
        }
    }

    if (tid < 128) lred[tid] = l_priv;
    __syncthreads();
    if (tid < 8) {
        int h = tid;
        float s = 0.f;
        #pragma unroll
        for (int row = 0; row < 16; row++)
            s += lred[(row & 7)*16 + (h >> 1)*4 + (row >> 3)*2 + (h & 1)];
        redg_add(&g_L[b*Hh + h], s);
    }
}

// ---------------- K2: vproj + gate + oproj + wout, one launch ----------------
// grid 576, 256 threads. x<512: vproj output x, gate (Wo prefetched), oproj.
// x>=512: weights-mean output half-batch.
__global__ void __launch_bounds__(256) k_vwo(const float* __restrict__ Wv,
                                             const float* __restrict__ Wo,
                                             float* __restrict__ out) {
    int x = blockIdx.x;
    int tid = threadIdx.x;
    if (x == 575 && tid == 0) g_gate2 = 0;      // reset k_qu2's gate for next replay
    if (x < 512) {
        int o = x, h = o >> 6;
        int w = tid >> 5, lane = tid & 31;
        // ---- prefetch BOTH weight rows up front (Wo loads overlap the gate spin) ----
        float4 wrV[4], wrO[4];
        #pragma unroll
        for (int k = 0; k < 4; k++) {
            wrV[k] = *(const float4*)&Wv[(size_t)o*Dd + k*128 + lane*4];
            wrO[k] = *(const float4*)&Wo[(size_t)o*Dd + k*128 + lane*4];
        }
        // ---- vproj ----
        #pragma unroll
        for (int i = 0; i < 4; i++) {
            int bb = w*4 + i;
            const float* ct = &g_cacc[((size_t)bb*Hh + h)*Dd];
            float4 e0 = __ldg((const float4*)&ct[0*128 + lane*4]);
            float4 e1 = __ldg((const float4*)&ct[1*128 + lane*4]);
            float4 e2 = __ldg((const float4*)&ct[2*128 + lane*4]);
            float4 e3 = __ldg((const float4*)&ct[3*128 + lane*4]);
            float s;
            s  = e0.x*wrV[0].x + e0.y*wrV[0].y + e0.z*wrV[0].z + e0.w*wrV[0].w;
            s += e1.x*wrV[1].x + e1.y*wrV[1].y + e1.z*wrV[1].z + e1.w*wrV[1].w;
            s += e2.x*wrV[2].x + e2.y*wrV[2].y + e2.z*wrV[2].z + e2.w*wrV[2].w;
            s += e3.x*wrV[3].x + e3.y*wrV[3].y + e3.z*wrV[3].z + e3.w*wrV[3].w;
            #pragma unroll
            for (int off = 16; off; off >>= 1) s += __shfl_xor_sync(0xffffffffu, s, off);
            if (lane == 0) g_ctx[(size_t)bb*Dd + o] = s / g_L[bb*Hh + h];
        }
        // ---- gate: all 512 vproj blocks done ----
        __threadfence();
        __syncthreads();
        if (tid == 0) {
            atomicAdd(&g_gate, 1);
            while (atomicAdd(&g_gate, 0) < 512) { }
        }
        __syncthreads();
        // ---- oproj (ctx via L2-coherent loads; Wo already in registers) ----
        #pragma unroll
        for (int i = 0; i < 4; i++) {
            int bb = w*4 + i;
            const float* ct = &g_ctx[(size_t)bb*Dd];
            float4 e0 = ldg_cg4(&ct[0*128 + lane*4]);
            float4 e1 = ldg_cg4(&ct[1*128 + lane*4]);
            float4 e2 = ldg_cg4(&ct[2*128 + lane*4]);
            float4 e3 = ldg_cg4(&ct[3*128 + lane*4]);
            float s;
            s  = e0.x*wrO[0].x + e0.y*wrO[0].y + e0.z*wrO[0].z + e0.w*wrO[0].w;
            s += e1.x*wrO[1].x + e1.y*wrO[1].y + e1.z*wrO[1].z + e1.w*wrO[1].w;
            s += e2.x*wrO[2].x + e2.y*wrO[2].y + e2.z*wrO[2].z + e2.w*wrO[2].w;
            s += e3.x*wrO[3].x + e3.y*wrO[3].y + e3.z*wrO[3].z + e3.w*wrO[3].w;
            #pragma unroll
            for (int off = 16; off; off >>= 1) s += __shfl_xor_sync(0xffffffffu, s, off);
            if (lane == 0) out[(size_t)bb*Dd + x] = s;
        }
    } else {
        int id = x - 512;            // 0..63
        int b = id >> 1, half = id & 1;
        __shared__ float iL[8];
        if (tid < 8) iL[tid] = 1.f / g_L[b*Hh + tid];
        __syncthreads();
        float i0 = iL[0], i1 = iL[1], i2 = iL[2], i3 = iL[3];
        float i4 = iL[4], i5 = iL[5], i6 = iL[6], i7 = iL[7];
        int t0 = half * (Tt/2);
        #pragma unroll
        for (int r = 0; r < (Tt/2)/256; r++) {
            int t = t0 + tid + r*256;
            const float4* pp = (const float4*)&g_scores[((size_t)b*Tt + t)*Hh];
            float4 a = pp[0], cc = pp[1];
            float s = __expf(a.x)*i0 + __expf(a.y)*i1
                    + __expf(a.z)*i2 + __expf(a.w)*i3
                    + __expf(cc.x)*i4 + __expf(cc.y)*i5
                    + __expf(cc.z)*i6 + __expf(cc.w)*i7;
            out[(size_t)Bb*Dd + (size_t)b*Tt + t] = s * (1.0f/Hh);
        }
    }
}

// ---------------- launch ----------------
extern "C" void kernel_launch(void* const* d_in, const int* in_sizes, int n_in,
                              void* d_out, int out_size) {
    const float* enc = (const float*)d_in[0];
    const float* Wq  = (const float*)d_in[1];
    const float* Wk  = (const float*)d_in[2];
    const float* Wv  = (const float*)d_in[3];
    const float* Wo  = (const float*)d_in[4];
    float* out = (float*)d_out;
    (void)in_sizes; (void)n_in; (void)out_size;

    cudaFuncSetAttribute(k_fused, cudaFuncAttributeMaxDynamicSharedMemorySize, FUSED_SMEM);
    cudaFuncSetAttribute(k_qu2, cudaFuncAttributeMaxDynamicSharedMemorySize, Bb*Dd*4);

    k_qu2    <<<320, 256, Bb*Dd*4>>>(enc, Wq, Wk);
    k_fused  <<<Bb*NC2, 256, FUSED_SMEM>>>(enc);
    k_vwo    <<<576, 256>>>(Wv, Wo, out);
}

// round 17
// speedup vs baseline: 1.0832x; 1.0832x over previous
#include <cuda_runtime.h>
#include <cstdint>

#define Bb 32
#define Tt 4096
#define Dd 512
#define Hh 8
#define HD 64
#define SCALE 0.125f

#define TILE 16
#define NC2 32
#define CH2 (Tt/NC2)        // 128 tokens per chunk
#define NTILES (CH2/TILE)   // 8 tiles

typedef unsigned long long ull;

// ---------------- helpers ----------------
__device__ __forceinline__ uint32_t s2u(const void* p) {
    uint32_t a; asm("{ .reg .u64 t; cvta.to.shared.u64 t, %1; cvt.u32.u64 %0, t; }" : "=r"(a) : "l"(p));
    return a;
}
__device__ __forceinline__ float lds32f(uint32_t addr) {
    float v; asm("ld.shared.f32 %0,[%1];" : "=f"(v) : "r"(addr)); return v;
}
__device__ __forceinline__ uint32_t lds32u(uint32_t addr) {
    uint32_t v; asm("ld.shared.b32 %0,[%1];" : "=r"(v) : "r"(addr)); return v;
}
__device__ __forceinline__ uint32_t f2tf(float f) {
    uint32_t r; asm("cvt.rna.tf32.f32 %0,%1;" : "=r"(r) : "f"(f)); return r;
}
__device__ __forceinline__ void cp16(uint32_t smem, const void* g) {
    asm volatile("cp.async.cg.shared.global [%0], [%1], 16;" :: "r"(smem), "l"(g) : "memory");
}
__device__ __forceinline__ void cp_commit() {
    asm volatile("cp.async.commit_group;" ::: "memory");
}
__device__ __forceinline__ void cp_wait1() {
    asm volatile("cp.async.wait_group 1;" ::: "memory");
}
__device__ __forceinline__ void redg_add(float* p, float v) {
    asm volatile("red.global.add.f32 [%0], %1;" :: "l"(p), "f"(v) : "memory");
}
__device__ __forceinline__ float4 ldg_cg4(const float* p) {
    float4 v;
    asm volatile("ld.global.cg.v4.f32 {%0,%1,%2,%3},[%4];"
        : "=f"(v.x), "=f"(v.y), "=f"(v.z), "=f"(v.w) : "l"(p));
    return v;
}
__device__ __forceinline__ void mma_tf32(float& c0, float& c1, float& c2, float& c3,
                                         uint32_t a0, uint32_t a1, uint32_t a2, uint32_t a3,
                                         uint32_t b0, uint32_t b1) {
    asm volatile("mma.sync.aligned.m16n8k8.row.col.f32.tf32.tf32.f32 "
                 "{%0,%1,%2,%3},{%4,%5,%6,%7},{%8,%9},{%0,%1,%2,%3};"
                 : "+f"(c0), "+f"(c1), "+f"(c2), "+f"(c3)
                 : "r"(a0), "r"(a1), "r"(a2), "r"(a3), "r"(b0), "r"(b1));
}

// ---------------- static scratch ----------------
__device__ float g_q[Bb*Dd];
__device__ float g_u[Bb*Hh*Dd];                 // SCALE folded in
__device__ float g_scores[(size_t)Bb*Tt*Hh];    // raw logits, 4MB
__device__ float g_L[Bb*Hh];                    // atomically accumulated
__device__ float g_cacc[Bb*Hh*Dd];              // atomically accumulated ctilde (unnorm)
__device__ float g_ctx[Bb*Dd];
__device__ int   g_gate;

// ---------------- K0a: q[b,o] = Wq[o,:] . enc[b,T-1,:]  (Wq read once) ----------------
__global__ void __launch_bounds__(256) k_q(const float* __restrict__ enc,
                                           const float* __restrict__ Wq) {
    extern __shared__ float esh[];
    int tid = threadIdx.x, w = tid >> 5, lane = tid & 31;
    {
        float4* dst = (float4*)esh;
        #pragma unroll
        for (int i = 0; i < 16; i++) {
            int idx = tid + i*256;
            int bb = idx >> 7, j4 = idx & 127;
            dst[idx] = *(const float4*)&enc[((size_t)bb*Tt + (Tt-1))*Dd + j4*4];
        }
    }
    int o = blockIdx.x*8 + w;
    float4 wr[4];
    #pragma unroll
    for (int k = 0; k < 4; k++)
        wr[k] = *(const float4*)&Wq[(size_t)o*Dd + k*128 + lane*4];
    __syncthreads();
    for (int bb = 0; bb < Bb; bb++) {
        float4 e0 = *(const float4*)&esh[bb*Dd + 0*128 + lane*4];
        float4 e1 = *(const float4*)&esh[bb*Dd + 1*128 + lane*4];
        float4 e2 = *(const float4*)&esh[bb*Dd + 2*128 + lane*4];
        float4 e3 = *(const float4*)&esh[bb*Dd + 3*128 + lane*4];
        float s;
        s  = e0.x*wr[0].x + e0.y*wr[0].y + e0.z*wr[0].z + e0.w*wr[0].w;
        s += e1.x*wr[1].x + e1.y*wr[1].y + e1.z*wr[1].z + e1.w*wr[1].w;
        s += e2.x*wr[2].x + e2.y*wr[2].y + e2.z*wr[2].z + e2.w*wr[2].w;
        s += e3.x*wr[3].x + e3.y*wr[3].y + e3.z*wr[3].z + e3.w*wr[3].w;
        #pragma unroll
        for (int off = 16; off; off >>= 1) s += __shfl_xor_sync(0xffffffffu, s, off);
        if (lane == 0) g_q[bb*Dd + o] = s;
    }
}

// ---------------- K0b: u + zero the atomic accumulators ----------------
__global__ void k_u(const float* __restrict__ Wk) {
    int h = blockIdx.x, b = blockIdx.y;
    int j = threadIdx.x;
    g_cacc[((size_t)b*Hh + h)*Dd + j] = 0.f;     // replay-safe re-zero
    if (j == 0) g_L[b*Hh + h] = 0.f;
    if (blockIdx.x == 0 && blockIdx.y == 0 && j == 0) g_gate = 0;
    __shared__ float qsh[HD];
    if (j < HD) qsh[j] = g_q[b*Dd + h*HD + j];
    __syncthreads();
    float s = 0.f;
    #pragma unroll 8
    for (int i = 0; i < HD; i++)
        s += Wk[((size_t)(h*HD + i))*Dd + j] * qsh[i];
    g_u[((size_t)b*Hh + h)*Dd + j] = s * SCALE;
}

// ---------------- smem layout of k_fused (float offsets) ----------------
// esh[2][16][512] swizzled   @ 0      (16384 floats)
// csh[8][128]                @ 16384  (1024)
// ew[16][12] (tf32 bits)     @ 17408  (192)
// lred[128]                  @ 17664  (128)
#define OFF_CSH  16384
#define OFF_EW   17408
#define OFF_LRED 17664
#define FUSED_SMEM (17792*4)

// Swizzle: element (t, d) stored at float-index  t*512 + ((q ^ (t&7))<<2) + (d&3),  q = d>>2.

// ---------------- K1: tf32-MMA scores + exp + tf32-MMA weighted accumulate ----------------
__global__ void __launch_bounds__(256, 3) k_fused(const float* __restrict__ enc) {
    extern __shared__ float sm[];
    uint32_t base_u = s2u(sm);
    uint32_t esh_u0 = base_u;
    uint32_t csh_u  = base_u + OFF_CSH*4;
    uint32_t ew_u   = base_u + OFF_EW*4;
    float* csh  = sm + OFF_CSH;
    float* lred = sm + OFF_LRED;
    uint32_t* smu = (uint32_t*)sm;

    int tid = threadIdx.x, w = tid >> 5, lane = tid & 31;
    int b = blockIdx.x >> 5, c = blockIdx.x & (NC2-1);
    int g  = lane >> 2;         // mma group id
    int tg = lane & 3;          // thread-in-group

    // ---- score-phase B fragments: U k-slice [w*64, w*64+64), tf32 (rounded once) ----
    uint32_t bf0[8], bf1[8];
    {
        const float* ub = &g_u[(size_t)b*Hh*Dd];   // [h][d]
        #pragma unroll
        for (int ks = 0; ks < 8; ks++) {
            int d = w*64 + ks*8 + tg;
            bf0[ks] = f2tf(ub[(size_t)g*Dd + d]);
            bf1[ks] = f2tf(ub[(size_t)g*Dd + d + 4]);
        }
    }

    int tbase = c * CH2;
    const float* encb = enc + ((size_t)b*Tt + tbase)*Dd;

    // ---- cp.async tile loader (swizzled) ----
    auto load_tile = [&](int tile) {
        const float* src = encb + (size_t)tile*TILE*Dd;
        #pragma unroll
        for (int j = 0; j < 8; j++) {
            int id = tid + j*256;          // 2048 chunks of 16B
            int t = id >> 7, q = id & 127;
            uint32_t saddr = esh_u0 + ((tile & 1) ? TILE*Dd*4 : 0)
                           + (uint32_t)(t*2048 + ((q ^ (t & 7)) << 4));
            cp16(saddr, src + (size_t)t*Dd + q*4);
        }
    };

    load_tile(0); cp_commit();
    load_tile(1); cp_commit();

    // ---- persistent context accumulators: warp w owns d in [w*64, w*64+64) ----
    float C[4][4];
    #pragma unroll
    for (int j = 0; j < 4; j++)
        #pragma unroll
        for (int r = 0; r < 4; r++) C[j][r] = 0.f;
    float l_priv = 0.f;

    for (int i = 0; i < NTILES; i++) {
        uint32_t esh_u = esh_u0 + (i & 1)*TILE*Dd*4;
        cp_wait1();
        __syncthreads();

        // ---- score phase: warp w = k-slice, mma m16n8k8 tf32 ----
        {
            float c0 = 0.f, c1 = 0.f, c2 = 0.f, c3 = 0.f;
            #pragma unroll
            for (int ks = 0; ks < 8; ks++) {
                uint32_t q  = (uint32_t)(w*16 + ks*2);
                uint32_t x0 = (q ^ (uint32_t)g) << 4;
                uint32_t x2 = ((q+1) ^ (uint32_t)g) << 4;
                uint32_t rb0 = esh_u + (uint32_t)(g*2048 + tg*4);
                uint32_t rb1 = esh_u + (uint32_t)((g+8)*2048 + tg*4);
                uint32_t a0 = f2tf(lds32f(rb0 + x0));
                uint32_t a1 = f2tf(lds32f(rb1 + x0));
                uint32_t a2 = f2tf(lds32f(rb0 + x2));
                uint32_t a3 = f2tf(lds32f(rb1 + x2));
                mma_tf32(c0, c1, c2, c3, a0, a1, a2, a3, bf0[ks], bf1[ks]);
            }
            asm volatile("st.shared.v4.f32 [%0],{%1,%2,%3,%4};"
                :: "r"(csh_u + (uint32_t)((w*128 + lane*4)*4)),
                   "f"(c0), "f"(c1), "f"(c2), "f"(c3) : "memory");
        }
        __syncthreads();

        // ---- reduce partials across warps, exp, publish tf32 weights (stride-12) ----
        if (tid < 128) {
            float s = csh[tid];
            #pragma unroll
            for (int ww = 1; ww < 8; ww++) s += csh[ww*128 + tid];
            int r = tid & 3, l2 = tid >> 2;
            int row = (l2 >> 2) + ((r >> 1) << 3);     // token row in tile
            int col = ((l2 & 3) << 1) + (r & 1);       // head
            g_scores[((size_t)b*Tt + tbase + i*TILE + row)*Hh + col] = s;
            float we = __expf(s);
            l_priv += we;
            smu[OFF_EW + row*12 + col] = f2tf(we);     // pre-converted tf32 bits
        }
        __syncthreads();

        // ---- accumulate via MMA: C(d x h) += E^T . W, k-permuted rows ----
        #pragma unroll
        for (int j = 0; j < 4; j++) {
            int mt = w*4 + j;
            #pragma unroll
            for (int ks = 0; ks < 2; ks++) {
                int r0 = ks*8 + 2*tg;
                int r1 = r0 + 1;
                int q0 = mt*4 + (g >> 2);
                int q1 = q0 + 2;
                uint32_t base0 = esh_u + (uint32_t)(r0*2048 + (g & 3)*4);
                uint32_t base1 = esh_u + (uint32_t)(r1*2048 + (g & 3)*4);
                uint32_t a0 = f2tf(lds32f(base0 + (uint32_t)(((q0 ^ (r0 & 7)) << 4))));
                uint32_t a1 = f2tf(lds32f(base0 + (uint32_t)(((q1 ^ (r0 & 7)) << 4))));
                uint32_t a2 = f2tf(lds32f(base1 + (uint32_t)(((q0 ^ (r1 & 7)) << 4))));
                uint32_t a3 = f2tf(lds32f(base1 + (uint32_t)(((q1 ^ (r1 & 7)) << 4))));
                uint32_t b0 = lds32u(ew_u + (uint32_t)((r0*12 + g)*4));
                uint32_t b1 = lds32u(ew_u + (uint32_t)((r1*12 + g)*4));
                mma_tf32(C[j][0], C[j][1], C[j][2], C[j][3], a0, a1, a2, a3, b0, b1);
            }
        }
        __syncthreads();   // buffer (i&1) fully consumed

        if (i + 2 < NTILES) load_tile(i + 2);
        cp_commit();       // uniform group count even when no loads issued
    }

    // ---- chunk outputs: RED.ADD C frags into g_cacc ----
    {
        float* pb = &g_cacc[((size_t)b*Hh)*Dd];
        #pragma unroll
        for (int j = 0; j < 4; j++) {
            int d = (w*4 + j)*16 + g;
            redg_add(&pb[(size_t)(2*tg)*Dd + d],       C[j][0]);
            redg_add(&pb[(size_t)(2*tg+1)*Dd + d],     C[j][1]);
            redg_add(&pb[(size_t)(2*tg)*Dd + d + 8],   C[j][2]);
            redg_add(&pb[(size_t)(2*tg+1)*Dd + d + 8], C[j][3]);
        }
    }

    if (tid < 128) lred[tid] = l_priv;
    __syncthreads();
    if (tid < 8) {
        int h = tid;
        float s = 0.f;
        #pragma unroll
        for (int row = 0; row < 16; row++)
            s += lred[(row & 7)*16 + (h >> 1)*4 + (row >> 3)*2 + (h & 1)];
        redg_add(&g_L[b*Hh + h], s);
    }
}

// ---------------- K2: vproj + gate + oproj + wout, one launch ----------------
// grid 576, 256 threads. x<512: vproj output x, gate (Wo prefetched), oproj.
// x>=512: weights-mean output half-batch.
__global__ void __launch_bounds__(256) k_vwo(const float* __restrict__ Wv,
                                             const float* __restrict__ Wo,
                                             float* __restrict__ out) {
    int x = blockIdx.x;
    int tid = threadIdx.x;
    if (x < 512) {
        int o = x, h = o >> 6;
        int w = tid >> 5, lane = tid & 31;
        // ---- prefetch BOTH weight rows up front (Wo loads overlap the gate spin) ----
        float4 wrV[4], wrO[4];
        #pragma unroll
        for (int k = 0; k < 4; k++) {
            wrV[k] = *(const float4*)&Wv[(size_t)o*Dd + k*128 + lane*4];
            wrO[k] = *(const float4*)&Wo[(size_t)o*Dd + k*128 + lane*4];
        }
        // ---- vproj ----
        #pragma unroll
        for (int i = 0; i < 4; i++) {
            int bb = w*4 + i;
            const float* ct = &g_cacc[((size_t)bb*Hh + h)*Dd];
            float4 e0 = __ldg((const float4*)&ct[0*128 + lane*4]);
            float4 e1 = __ldg((const float4*)&ct[1*128 + lane*4]);
            float4 e2 = __ldg((const float4*)&ct[2*128 + lane*4]);
            float4 e3 = __ldg((const float4*)&ct[3*128 + lane*4]);
            float s;
            s  = e0.x*wrV[0].x + e0.y*wrV[0].y + e0.z*wrV[0].z + e0.w*wrV[0].w;
            s += e1.x*wrV[1].x + e1.y*wrV[1].y + e1.z*wrV[1].z + e1.w*wrV[1].w;
            s += e2.x*wrV[2].x + e2.y*wrV[2].y + e2.z*wrV[2].z + e2.w*wrV[2].w;
            s += e3.x*wrV[3].x + e3.y*wrV[3].y + e3.z*wrV[3].z + e3.w*wrV[3].w;
            #pragma unroll
            for (int off = 16; off; off >>= 1) s += __shfl_xor_sync(0xffffffffu, s, off);
            if (lane == 0) g_ctx[(size_t)bb*Dd + o] = s / g_L[bb*Hh + h];
        }
        // ---- gate: all 512 vproj blocks done ----
        __threadfence();
        __syncthreads();
        if (tid == 0) {
            atomicAdd(&g_gate, 1);
            while (atomicAdd(&g_gate, 0) < 512) { }
        }
        __syncthreads();
        // ---- oproj (ctx via L2-coherent loads; Wo already in registers) ----
        #pragma unroll
        for (int i = 0; i < 4; i++) {
            int bb = w*4 + i;
            const float* ct = &g_ctx[(size_t)bb*Dd];
            float4 e0 = ldg_cg4(&ct[0*128 + lane*4]);
            float4 e1 = ldg_cg4(&ct[1*128 + lane*4]);
            float4 e2 = ldg_cg4(&ct[2*128 + lane*4]);
            float4 e3 = ldg_cg4(&ct[3*128 + lane*4]);
            float s;
            s  = e0.x*wrO[0].x + e0.y*wrO[0].y + e0.z*wrO[0].z + e0.w*wrO[0].w;
            s += e1.x*wrO[1].x + e1.y*wrO[1].y + e1.z*wrO[1].z + e1.w*wrO[1].w;
            s += e2.x*wrO[2].x + e2.y*wrO[2].y + e2.z*wrO[2].z + e2.w*wrO[2].w;
            s += e3.x*wrO[3].x + e3.y*wrO[3].y + e3.z*wrO[3].z + e3.w*wrO[3].w;
            #pragma unroll
            for (int off = 16; off; off >>= 1) s += __shfl_xor_sync(0xffffffffu, s, off);
            if (lane == 0) out[(size_t)bb*Dd + x] = s;
        }
    } else {
        int id = x - 512;            // 0..63
        int b = id >> 1, half = id & 1;
        __shared__ float iL[8];
        if (tid < 8) iL[tid] = 1.f / g_L[b*Hh + tid];
        __syncthreads();
        float i0 = iL[0], i1 = iL[1], i2 = iL[2], i3 = iL[3];
        float i4 = iL[4], i5 = iL[5], i6 = iL[6], i7 = iL[7];
        int t0 = half * (Tt/2);
        #pragma unroll
        for (int r = 0; r < (Tt/2)/256; r++) {
            int t = t0 + tid + r*256;
            const float4* pp = (const float4*)&g_scores[((size_t)b*Tt + t)*Hh];
            float4 a = pp[0], cc = pp[1];
            float s = __expf(a.x)*i0 + __expf(a.y)*i1
                    + __expf(a.z)*i2 + __expf(a.w)*i3
                    + __expf(cc.x)*i4 + __expf(cc.y)*i5
                    + __expf(cc.z)*i6 + __expf(cc.w)*i7;
            out[(size_t)Bb*Dd + (size_t)b*Tt + t] = s * (1.0f/Hh);
        }
    }
}

// ---------------- launch ----------------
extern "C" void kernel_launch(void* const* d_in, const int* in_sizes, int n_in,
                              void* d_out, int out_size) {
    const float* enc = (const float*)d_in[0];
    const float* Wq  = (const float*)d_in[1];
    const float* Wk  = (const float*)d_in[2];
    const float* Wv  = (const float*)d_in[3];
    const float* Wo  = (const float*)d_in[4];
    float* out = (float*)d_out;
    (void)in_sizes; (void)n_in; (void)out_size;

    cudaFuncSetAttribute(k_fused, cudaFuncAttributeMaxDynamicSharedMemorySize, FUSED_SMEM);
    cudaFuncSetAttribute(k_q, cudaFuncAttributeMaxDynamicSharedMemorySize, Bb*Dd*4);

    k_q      <<<64, 256, Bb*Dd*4>>>(enc, Wq);
    k_u      <<<dim3(Hh, Bb), Dd>>>(Wk);
    k_fused  <<<Bb*NC2, 256, FUSED_SMEM>>>(enc);
    k_vwo    <<<576, 256>>>(Wv, Wo, out);
}